// round 1
// baseline (speedup 1.0000x reference)
#include <cuda_runtime.h>

#define T_ 32
#define H_ 56
#define W_ 56
#define C_ 64
#define B_ 4
#define TILEH 8
#define NTILES 7          // 56 / TILEH
#define NT 224            // 28 w-pairs * 8 rows = 7 warps
#define RS 60             // padded row stride (floats) -> 240B, 16B aligned
#define PR (TILEH + 2)    // rows per staged plane (halo)
#define SLOTS 5           // smem plane ring depth
#define PLANEF (PR * RS)  // 600 floats per staged plane

__device__ __forceinline__ float siggate(float v) {
    // sigmoid(v) - 0.5 via fast MUFU path (EX2 + RCP)
    return __fdividef(1.0f, 1.0f + __expf(-v)) - 0.5f;
}

__global__ void __launch_bounds__(NT, 2) tts_kernel(
    const float* __restrict__ xg,
    const float* __restrict__ w1g, const float* __restrict__ b1g,
    const float* __restrict__ w2g, const float* __restrict__ b2g,
    const float* __restrict__ w3g, const float* __restrict__ b3g,
    const float* __restrict__ wgg,
    float* __restrict__ outg)
{
    __shared__ __align__(16) float plane[SLOTS][PR][RS];
    __shared__ __align__(16) float wsm[9][12];   // [conv*3+slice][9 taps + pad]
    __shared__ float bsm[3];
    __shared__ float gsm[3];

    const int tid  = threadIdx.x;
    const int bx   = blockIdx.x;
    const int tile = bx % NTILES;
    const int bc   = bx / NTILES;      // b*C + c
    const int c    = bc % C_;
    const int h0   = tile * TILEH;

    const float* __restrict__ xin = xg + (size_t)bc * (T_ * H_ * W_);
    float* __restrict__ op = outg + (size_t)bc * (T_ * H_ * W_);

    // Stage channel weights: slice-major, 12-float stride (16B-aligned rows)
    for (int idx = tid; idx < 108; idx += NT) {
        int sl = idx / 12, tap = idx % 12;
        int i = sl / 3, s = sl % 3;
        const float* wp = (i == 0) ? w1g : (i == 1) ? w2g : w3g;
        wsm[sl][tap] = (tap < 9) ? wp[c * 27 + s * 9 + tap] : 0.0f;
    }
    if (tid < 3) {
        bsm[tid] = ((tid == 0) ? b1g : (tid == 1) ? b2g : b3g)[c];
        gsm[tid] = wgg[tid];
    }

    // Plane-staging geometry (tau-independent; hoisted)
    int goff[3], soff[3];
    bool inb[3], act[3];
    #pragma unroll
    for (int k = 0; k < 3; ++k) {
        int idx = tid + k * NT;
        act[k] = (idx < PLANEF);
        int r = idx / RS, col = idx % RS;
        int y = h0 - 1 + r, xw = col - 1;
        inb[k] = act[k] && (y >= 0) && (y < H_) && (xw >= 0) && (xw < W_);
        goff[k] = y * W_ + xw;
        soff[k] = r * RS + col;
    }

    // Prologue: stage plane 0 into slot 0
    #pragma unroll
    for (int k = 0; k < 3; ++k)
        if (act[k]) plane[0][0][soff[k]] = inb[k] ? xin[goff[k]] : 0.0f;
    __syncthreads();

    const float bias0 = bsm[0], bias1 = bsm[1], bias2 = bsm[2];
    const float wt0 = gsm[0], wt1 = gsm[1], wt2 = gsm[2];

    const int row   = tid / 28;          // 0..7
    const int w0    = (tid % 28) * 2;    // 0..54, 2 pixels per thread
    const int nb0   = row * RS + w0;     // neighborhood base (dy = -1 row)
    const int obase = (h0 + row) * W_ + w0;

    // Shift-register accumulator rings: a_i[j] holds y_i(tau + d_i - j).
    float2 a1[3], a2[5], a3[7], g4[4];
    float2 h1, h2[2], h3[3];
    #pragma unroll
    for (int j = 0; j < 3; ++j) a1[j] = make_float2(0.f, 0.f);
    #pragma unroll
    for (int j = 0; j < 5; ++j) a2[j] = make_float2(0.f, 0.f);
    #pragma unroll
    for (int j = 0; j < 7; ++j) a3[j] = make_float2(0.f, 0.f);
    #pragma unroll
    for (int j = 0; j < 4; ++j) g4[j] = make_float2(0.f, 0.f);
    h1 = make_float2(0.f, 0.f);
    h2[0] = h2[1] = make_float2(0.f, 0.f);
    h3[0] = h3[1] = h3[2] = make_float2(0.f, 0.f);

    #pragma unroll 1
    for (int tau = 0; tau < T_ + 3; ++tau) {
        __syncthreads();  // slot (tau%5) staged by previous iteration

        if (tau < T_) {
            // Issue next-plane global loads first so they overlap compute.
            float pf[3];
            const bool pref = (tau + 1 < T_);
            if (pref) {
                const float* src = xin + (size_t)(tau + 1) * (H_ * W_);
                #pragma unroll
                for (int k = 0; k < 3; ++k)
                    pf[k] = inb[k] ? src[goff[k]] : 0.0f;
            }

            const float* pl = &plane[tau % SLOTS][0][0];
            float xn[3][4];
            #pragma unroll
            for (int dy = 0; dy < 3; ++dy) {
                float2 p01 = *(const float2*)(pl + nb0 + dy * RS);
                float2 p23 = *(const float2*)(pl + nb0 + dy * RS + 2);
                xn[dy][0] = p01.x; xn[dy][1] = p01.y;
                xn[dy][2] = p23.x; xn[dy][3] = p23.y;
            }

            auto SL = [&](int sl, float2& acc) {
                const float4* wq = (const float4*)wsm[sl];
                float4 wa = wq[0];
                float4 wb = wq[1];
                float  w8 = wsm[sl][8];
                float wv[9] = {wa.x, wa.y, wa.z, wa.w, wb.x, wb.y, wb.z, wb.w, w8};
                #pragma unroll
                for (int dy = 0; dy < 3; ++dy) {
                    #pragma unroll
                    for (int dx = 0; dx < 3; ++dx) {
                        float w = wv[dy * 3 + dx];
                        acc.x = fmaf(w, xn[dy][dx],     acc.x);
                        acc.y = fmaf(w, xn[dy][dx + 1], acc.y);
                    }
                }
            };

            // slice s contributes to time t = tau - (s-1)*d  ->  ring slot s*d.
            // Out-of-range targets accumulate garbage that ring shifts discard
            // before any read: no per-slice branches needed.
            SL(0, a1[0]); SL(1, a1[1]); SL(2, a1[2]);
            SL(3, a2[0]); SL(4, a2[2]); SL(5, a2[4]);
            SL(6, a3[0]); SL(7, a3[3]); SL(8, a3[6]);

            if (pref) {
                float* dst = &plane[(tau + 1) % SLOTS][0][0];
                #pragma unroll
                for (int k = 0; k < 3; ++k)
                    if (act[k]) dst[soff[k]] = pf[k];
            }
        }

        // Completions: y_i(tau - d_i) finishes this step.
        if (tau >= 1 && tau <= T_) {             // c = tau-1 in [0,T)
            float2 yv = make_float2(a1[2].x + bias0, a1[2].y + bias0);
            float2 dv = yv;
            if (tau >= 2) { dv.x -= h1.x; dv.y -= h1.y; }   // c >= 1
            h1 = yv;
            g4[1].x += siggate(dv.x) * wt0;
            g4[1].y += siggate(dv.y) * wt0;
        }
        if (tau >= 2 && tau <= T_ + 1) {         // c = tau-2
            float2 yv = make_float2(a2[4].x + bias1, a2[4].y + bias1);
            float2 dv = yv;
            if (tau >= 4) { dv.x -= h2[1].x; dv.y -= h2[1].y; }  // c >= 2
            h2[1] = h2[0]; h2[0] = yv;
            g4[2].x += siggate(dv.x) * wt1;
            g4[2].y += siggate(dv.y) * wt1;
        }
        if (tau >= 3) {                          // c = tau-3 (<= T-1 by bound)
            float2 yv = make_float2(a3[6].x + bias2, a3[6].y + bias2);
            float2 dv = yv;
            if (tau >= 6) { dv.x -= h3[2].x; dv.y -= h3[2].y; }  // c >= 3
            h3[2] = h3[1]; h3[1] = h3[0]; h3[0] = yv;
            float2 gt = g4[3];
            gt.x += siggate(dv.x) * wt2;
            gt.y += siggate(dv.y) * wt2;

            // Output for t = tau-3: gate complete; center x still in plane ring.
            const int tout = tau - 3;
            const float* pc = &plane[(tau + 2) % SLOTS][0][0];  // slot of plane tau-3
            float cx0 = pc[nb0 + RS + 1];
            float cx1 = pc[nb0 + RS + 2];
            float2 o = make_float2(cx0 * gt.x, cx1 * gt.y);
            *(float2*)(op + (size_t)tout * (H_ * W_) + obase) = o;
        }

        // Shift rings (constant indices -> pure register MOVs on alu pipe)
        a1[2] = a1[1]; a1[1] = a1[0]; a1[0] = make_float2(0.f, 0.f);
        a2[4] = a2[3]; a2[3] = a2[2]; a2[2] = a2[1]; a2[1] = a2[0];
        a2[0] = make_float2(0.f, 0.f);
        a3[6] = a3[5]; a3[5] = a3[4]; a3[4] = a3[3]; a3[3] = a3[2];
        a3[2] = a3[1]; a3[1] = a3[0]; a3[0] = make_float2(0.f, 0.f);
        g4[3] = g4[2]; g4[2] = g4[1]; g4[1] = g4[0]; g4[0] = make_float2(0.f, 0.f);
    }
}

extern "C" void kernel_launch(void* const* d_in, const int* in_sizes, int n_in,
                              void* d_out, int out_size) {
    const float* x  = (const float*)d_in[0];
    const float* w1 = (const float*)d_in[1];
    const float* b1 = (const float*)d_in[2];
    const float* w2 = (const float*)d_in[3];
    const float* b2 = (const float*)d_in[4];
    const float* w3 = (const float*)d_in[5];
    const float* b3 = (const float*)d_in[6];
    const float* wg = (const float*)d_in[7];
    float* out = (float*)d_out;

    dim3 grid(B_ * C_ * NTILES);   // 4*64*7 = 1792 blocks
    dim3 block(NT);                // 224 threads
    tts_kernel<<<grid, block>>>(x, w1, b1, w2, b2, w3, b3, wg, out);
}

// round 2
// speedup vs baseline: 1.6175x; 1.6175x over previous
#include <cuda_runtime.h>

#define T_ 32
#define H_ 56
#define W_ 56
#define C_ 64
#define B_ 4
#define TILEH 8
#define NTILES 7          // 56 / TILEH
#define NT 224            // 28 w-pairs * 8 rows = 7 warps
#define RS 60             // padded row stride (floats)
#define PR (TILEH + 2)    // rows per staged plane (halo)
#define SLOTS 5           // smem plane ring depth
#define PLANEF (PR * RS)  // 600 floats per staged plane

__device__ __forceinline__ float siggate(float v) {
    // sigmoid(v) - 0.5 via MUFU EX2 + RCP
    return __fdividef(1.0f, 1.0f + __expf(-v)) - 0.5f;
}

__global__ void __launch_bounds__(NT, 3) tts_kernel(
    const float* __restrict__ xg,
    const float* __restrict__ w1g, const float* __restrict__ b1g,
    const float* __restrict__ w2g, const float* __restrict__ b2g,
    const float* __restrict__ w3g, const float* __restrict__ b3g,
    const float* __restrict__ wgg,
    float* __restrict__ outg)
{
    __shared__ __align__(16) float plane[SLOTS][PR][RS];
    __shared__ __align__(16) float wsm[9][12];   // [conv*3+slice][9 taps + pad]
    __shared__ float bsm[3];
    __shared__ float gsm[3];

    const int tid  = threadIdx.x;
    const int bx   = blockIdx.x;
    const int tile = bx % NTILES;
    const int bc   = bx / NTILES;      // b*C + c
    const int c    = bc % C_;
    const int h0   = tile * TILEH;

    const float* __restrict__ xin = xg + (size_t)bc * (T_ * H_ * W_);
    float* __restrict__ op = outg + (size_t)bc * (T_ * H_ * W_);

    // Stage channel weights: slice-major, 12-float stride
    for (int idx = tid; idx < 108; idx += NT) {
        int sl = idx / 12, tap = idx % 12;
        int i = sl / 3, s = sl % 3;
        const float* wp = (i == 0) ? w1g : (i == 1) ? w2g : w3g;
        wsm[sl][tap] = (tap < 9) ? wp[c * 27 + s * 9 + tap] : 0.0f;
    }
    if (tid < 3) {
        bsm[tid] = ((tid == 0) ? b1g : (tid == 1) ? b2g : b3g)[c];
        gsm[tid] = wgg[tid];
    }

    // Plane-staging geometry (tau-independent)
    int goff[3], soff[3];
    bool inb[3], act[3];
    #pragma unroll
    for (int k = 0; k < 3; ++k) {
        int idx = tid + k * NT;
        act[k] = (idx < PLANEF);
        int r = idx / RS, col = idx % RS;
        int y = h0 - 1 + r, xw = col - 1;
        inb[k] = act[k] && (y >= 0) && (y < H_) && (xw >= 0) && (xw < W_);
        goff[k] = y * W_ + xw;
        soff[k] = r * RS + col;
    }

    // Prologue: stage plane 0 into slot 0
    #pragma unroll
    for (int k = 0; k < 3; ++k)
        if (act[k]) plane[0][0][soff[k]] = inb[k] ? xin[goff[k]] : 0.0f;
    __syncthreads();

    const float bias0 = bsm[0], bias1 = bsm[1], bias2 = bsm[2];
    const float wt0 = gsm[0], wt1 = gsm[1], wt2 = gsm[2];

    const int row   = tid / 28;          // 0..7
    const int w0    = (tid % 28) * 2;    // 0..54, 2 pixels per thread
    const int nb0   = row * RS + w0;     // neighborhood base (dy = -1 row)
    const int obase = (h0 + row) * W_ + w0;

    // Absolute-time modular accumulators. A_i[t mod k] holds partial y_i(t).
    // Consume-then-reset replaces all ring shifting; with the loop fully
    // unrolled every index below is a compile-time constant -> pure SSA.
    float2 A1[3], A2[5], A3[7], G[3];
    float2 h1v, h2v[2], h3v[3];
    #pragma unroll
    for (int j = 0; j < 3; ++j) A1[j] = make_float2(0.f, 0.f);
    #pragma unroll
    for (int j = 0; j < 5; ++j) A2[j] = make_float2(0.f, 0.f);
    #pragma unroll
    for (int j = 0; j < 7; ++j) A3[j] = make_float2(0.f, 0.f);
    #pragma unroll
    for (int j = 0; j < 3; ++j) G[j] = make_float2(0.f, 0.f);
    h1v = make_float2(0.f, 0.f);
    h2v[0] = h2v[1] = make_float2(0.f, 0.f);
    h3v[0] = h3v[1] = h3v[2] = make_float2(0.f, 0.f);

    #pragma unroll
    for (int tau = 0; tau < T_ + 3; ++tau) {
        __syncthreads();  // slot (tau%5) staged by previous iteration

        if (tau < T_) {
            // Prefetch next plane (overlaps with compute below)
            float pf[3];
            const bool pref = (tau + 1 < T_);
            if (pref) {
                const float* src = xin + (size_t)(tau + 1) * (H_ * W_);
                #pragma unroll
                for (int k = 0; k < 3; ++k)
                    pf[k] = inb[k] ? src[goff[k]] : 0.0f;
            }

            const float* pl = &plane[tau % SLOTS][0][0];
            float xn[3][4];
            #pragma unroll
            for (int dy = 0; dy < 3; ++dy) {
                float2 p01 = *(const float2*)(pl + nb0 + dy * RS);
                float2 p23 = *(const float2*)(pl + nb0 + dy * RS + 2);
                xn[dy][0] = p01.x; xn[dy][1] = p01.y;
                xn[dy][2] = p23.x; xn[dy][3] = p23.y;
            }

            auto SL = [&](int sl, float2& acc) {
                const float4* wq = (const float4*)wsm[sl];
                float4 wa = wq[0];
                float4 wb = wq[1];
                float  w8 = wsm[sl][8];
                float wv[9] = {wa.x, wa.y, wa.z, wa.w, wb.x, wb.y, wb.z, wb.w, w8};
                #pragma unroll
                for (int dy = 0; dy < 3; ++dy) {
                    #pragma unroll
                    for (int dx = 0; dx < 3; ++dx) {
                        float w = wv[dy * 3 + dx];
                        acc.x = fmaf(w, xn[dy][dx],     acc.x);
                        acc.y = fmaf(w, xn[dy][dx + 1], acc.y);
                    }
                }
            };

            // conv i slice s applied to plane tau contributes to t = tau-(s-1)*d_i
            SL(0, A1[(tau + 1) % 3]);  // t = tau+1
            SL(1, A1[ tau      % 3]);  // t = tau
            SL(2, A1[(tau + 2) % 3]);  // t = tau-1
            SL(3, A2[(tau + 2) % 5]);  // t = tau+2
            SL(4, A2[ tau      % 5]);  // t = tau
            SL(5, A2[(tau + 3) % 5]);  // t = tau-2
            SL(6, A3[(tau + 3) % 7]);  // t = tau+3
            SL(7, A3[ tau      % 7]);  // t = tau
            SL(8, A3[(tau + 4) % 7]);  // t = tau-3

            if (pref) {
                float* dst = &plane[(tau + 1) % SLOTS][0][0];
                #pragma unroll
                for (int k = 0; k < 3; ++k)
                    if (act[k]) dst[soff[k]] = pf[k];
            }
        }

        // conv1 completes y1(tau-1); slot also reset on discard (tau==0)
        if (tau <= T_) {
            const int s1 = (tau + 2) % 3;
            if (tau >= 1) {
                float2 yv = make_float2(A1[s1].x + bias0, A1[s1].y + bias0);
                float2 dv = yv;
                if (tau >= 2) { dv.x -= h1v.x; dv.y -= h1v.y; }
                h1v = yv;
                const int gs = (tau + 2) % 3;   // t = tau-1
                G[gs].x += siggate(dv.x) * wt0;
                G[gs].y += siggate(dv.y) * wt0;
            }
            A1[s1] = make_float2(0.f, 0.f);
        }

        // conv2 completes y2(tau-2)
        if (tau <= T_ + 1) {
            const int s2 = (tau + 3) % 5;
            if (tau >= 2) {
                float2 yv = make_float2(A2[s2].x + bias1, A2[s2].y + bias1);
                float2 dv = yv;
                const int hs = tau % 2;         // t = tau-2 -> t%2 == tau%2
                if (tau >= 4) { dv.x -= h2v[hs].x; dv.y -= h2v[hs].y; }
                h2v[hs] = yv;
                const int gs = (tau + 1) % 3;   // t = tau-2
                G[gs].x += siggate(dv.x) * wt1;
                G[gs].y += siggate(dv.y) * wt1;
            }
            A2[s2] = make_float2(0.f, 0.f);
        }

        // conv3 completes y3(tau-3); gate for t=tau-3 done -> output
        {
            const int s3 = (tau + 4) % 7;
            if (tau >= 3) {
                float2 yv = make_float2(A3[s3].x + bias2, A3[s3].y + bias2);
                float2 dv = yv;
                const int hs = tau % 3;         // t = tau-3 -> t%3 == tau%3
                if (tau >= 6) { dv.x -= h3v[hs].x; dv.y -= h3v[hs].y; }
                h3v[hs] = yv;
                const int gs = tau % 3;         // t = tau-3
                float2 gt = G[gs];
                gt.x += siggate(dv.x) * wt2;
                gt.y += siggate(dv.y) * wt2;
                G[gs] = make_float2(0.f, 0.f);

                const int tout = tau - 3;
                const float* pc = &plane[(tau + 2) % SLOTS][0][0];  // plane tau-3
                float cx0 = pc[nb0 + RS + 1];
                float cx1 = pc[nb0 + RS + 2];
                float2 o = make_float2(cx0 * gt.x, cx1 * gt.y);
                *(float2*)(op + (size_t)tout * (H_ * W_) + obase) = o;
            }
            A3[s3] = make_float2(0.f, 0.f);
        }
    }
}

extern "C" void kernel_launch(void* const* d_in, const int* in_sizes, int n_in,
                              void* d_out, int out_size) {
    const float* x  = (const float*)d_in[0];
    const float* w1 = (const float*)d_in[1];
    const float* b1 = (const float*)d_in[2];
    const float* w2 = (const float*)d_in[3];
    const float* b2 = (const float*)d_in[4];
    const float* w3 = (const float*)d_in[5];
    const float* b3 = (const float*)d_in[6];
    const float* wg = (const float*)d_in[7];
    float* out = (float*)d_out;

    dim3 grid(B_ * C_ * NTILES);   // 4*64*7 = 1792 blocks
    dim3 block(NT);                // 224 threads
    tts_kernel<<<grid, block>>>(x, w1, b1, w2, b2, w3, b3, wg, out);
}

// round 3
// speedup vs baseline: 1.7681x; 1.0931x over previous
#include <cuda_runtime.h>

#define T_ 32
#define H_ 56
#define W_ 56
#define C_ 64
#define B_ 4
#define TILEH 8
#define NTILES 7          // 56 / TILEH
#define NT 224            // 28 w-pairs * 8 rows = 7 warps
#define RS 60             // padded row stride (floats)
#define PR (TILEH + 2)    // rows per staged plane (halo)
#define SLOTS 5           // smem plane ring depth
#define PLANEF (PR * RS)  // 600 floats per staged plane

__device__ __forceinline__ float siggate(float v) {
    // sigmoid(v) - 0.5 via MUFU EX2 + RCP
    return __fdividef(1.0f, 1.0f + __expf(-v)) - 0.5f;
}

__global__ void __launch_bounds__(NT, 4) tts_kernel(
    const float* __restrict__ xg,
    const float* __restrict__ w1g, const float* __restrict__ b1g,
    const float* __restrict__ w2g, const float* __restrict__ b2g,
    const float* __restrict__ w3g, const float* __restrict__ b3g,
    const float* __restrict__ wgg,
    float* __restrict__ outg)
{
    __shared__ __align__(16) float plane[SLOTS][PR][RS];
    __shared__ __align__(16) float wsm[9][12];   // [conv*3+slice][9 taps + pad]
    // Per-thread sigmoid-lag histories, demoted from registers to free ~12
    // regs for occupancy. SoA: [slot][tid] -> consecutive lanes contiguous,
    // conflict-free LDS.64/STS.64.  slots: 0=h1, 1..2=h2, 3..5=h3
    __shared__ __align__(16) float2 hsm[6][NT];
    __shared__ float bsm[3];
    __shared__ float gsm[3];

    const int tid  = threadIdx.x;
    const int bx   = blockIdx.x;
    const int tile = bx % NTILES;
    const int bc   = bx / NTILES;      // b*C + c
    const int c    = bc % C_;
    const int h0   = tile * TILEH;

    const float* __restrict__ xin = xg + (size_t)bc * (T_ * H_ * W_);
    float* __restrict__ op = outg + (size_t)bc * (T_ * H_ * W_);

    // Stage channel weights: slice-major, 12-float stride
    for (int idx = tid; idx < 108; idx += NT) {
        int sl = idx / 12, tap = idx % 12;
        int i = sl / 3, s = sl % 3;
        const float* wp = (i == 0) ? w1g : (i == 1) ? w2g : w3g;
        wsm[sl][tap] = (tap < 9) ? wp[c * 27 + s * 9 + tap] : 0.0f;
    }
    if (tid < 3) {
        bsm[tid] = ((tid == 0) ? b1g : (tid == 1) ? b2g : b3g)[c];
        gsm[tid] = wgg[tid];
    }

    // Plane-staging geometry (tau-independent). act[0],act[1] are always
    // true (NT*2 < PLANEF); only k=2 is partial.
    int goff[3], soff[3];
    bool inb[3];
    #pragma unroll
    for (int k = 0; k < 3; ++k) {
        int idx = tid + k * NT;
        bool a = (idx < PLANEF);
        int r = idx / RS, col = idx % RS;
        int y = h0 - 1 + r, xw = col - 1;
        inb[k] = a && (y >= 0) && (y < H_) && (xw >= 0) && (xw < W_);
        goff[k] = y * W_ + xw;
        soff[k] = a ? (r * RS + col) : 0;   // inactive threads write slot 0 harmlessly? no:
    }
    const bool act2 = (tid + 2 * NT) < PLANEF;

    // Prologue: stage plane 0 into slot 0
    plane[0][0][soff[0]] = inb[0] ? xin[goff[0]] : 0.0f;
    plane[0][0][soff[1]] = inb[1] ? xin[goff[1]] : 0.0f;
    if (act2) plane[0][0][soff[2]] = inb[2] ? xin[goff[2]] : 0.0f;

    // Init histories (read-before-first-write paths are guarded by tau
    // thresholds, but keep deterministic zeros anyway)
    #pragma unroll
    for (int j = 0; j < 6; ++j) hsm[j][tid] = make_float2(0.f, 0.f);

    __syncthreads();

    const float bias0 = bsm[0], bias1 = bsm[1], bias2 = bsm[2];
    const float wt0 = gsm[0], wt1 = gsm[1], wt2 = gsm[2];

    const int row   = tid / 28;          // 0..7
    const int w0    = (tid % 28) * 2;    // 0..54, 2 pixels per thread
    const int nb0   = row * RS + w0;     // neighborhood base (dy = -1 row)
    const int obase = (h0 + row) * W_ + w0;

    // Absolute-time modular accumulators; loop fully unrolled -> all
    // indices compile-time constants, accumulators pure SSA.
    float2 A1[3], A2[5], A3[7], G[3];
    #pragma unroll
    for (int j = 0; j < 3; ++j) A1[j] = make_float2(0.f, 0.f);
    #pragma unroll
    for (int j = 0; j < 5; ++j) A2[j] = make_float2(0.f, 0.f);
    #pragma unroll
    for (int j = 0; j < 7; ++j) A3[j] = make_float2(0.f, 0.f);
    #pragma unroll
    for (int j = 0; j < 3; ++j) G[j] = make_float2(0.f, 0.f);

    #pragma unroll
    for (int tau = 0; tau < T_ + 3; ++tau) {
        __syncthreads();  // slot (tau%5) staged by previous iteration

        if (tau < T_) {
            // Prefetch next plane (overlaps with compute below)
            float pf0, pf1, pf2;
            const bool pref = (tau + 1 < T_);
            if (pref) {
                const float* src = xin + (size_t)(tau + 1) * (H_ * W_);
                pf0 = inb[0] ? src[goff[0]] : 0.0f;
                pf1 = inb[1] ? src[goff[1]] : 0.0f;
                pf2 = inb[2] ? src[goff[2]] : 0.0f;
            }

            const float* pl = &plane[tau % SLOTS][0][0];
            float xn[3][4];
            #pragma unroll
            for (int dy = 0; dy < 3; ++dy) {
                float2 p01 = *(const float2*)(pl + nb0 + dy * RS);
                float2 p23 = *(const float2*)(pl + nb0 + dy * RS + 2);
                xn[dy][0] = p01.x; xn[dy][1] = p01.y;
                xn[dy][2] = p23.x; xn[dy][3] = p23.y;
            }

            auto SL = [&](int sl, float2& acc) {
                const float4* wq = (const float4*)wsm[sl];
                float4 wa = wq[0];
                float4 wb = wq[1];
                float  w8 = wsm[sl][8];
                float wv[9] = {wa.x, wa.y, wa.z, wa.w, wb.x, wb.y, wb.z, wb.w, w8};
                #pragma unroll
                for (int dy = 0; dy < 3; ++dy) {
                    #pragma unroll
                    for (int dx = 0; dx < 3; ++dx) {
                        float w = wv[dy * 3 + dx];
                        acc.x = fmaf(w, xn[dy][dx],     acc.x);
                        acc.y = fmaf(w, xn[dy][dx + 1], acc.y);
                    }
                }
            };

            // conv i slice s applied to plane tau contributes to t = tau-(s-1)*d_i
            SL(0, A1[(tau + 1) % 3]);  // t = tau+1
            SL(1, A1[ tau      % 3]);  // t = tau
            SL(2, A1[(tau + 2) % 3]);  // t = tau-1
            SL(3, A2[(tau + 2) % 5]);  // t = tau+2
            SL(4, A2[ tau      % 5]);  // t = tau
            SL(5, A2[(tau + 3) % 5]);  // t = tau-2
            SL(6, A3[(tau + 3) % 7]);  // t = tau+3
            SL(7, A3[ tau      % 7]);  // t = tau
            SL(8, A3[(tau + 4) % 7]);  // t = tau-3

            if (pref) {
                float* dst = &plane[(tau + 1) % SLOTS][0][0];
                dst[soff[0]] = pf0;
                dst[soff[1]] = pf1;
                if (act2) dst[soff[2]] = pf2;
            }
        }

        // conv1 completes y1(tau-1)
        if (tau <= T_) {
            const int s1 = (tau + 2) % 3;
            if (tau >= 1) {
                float2 yv = make_float2(A1[s1].x + bias0, A1[s1].y + bias0);
                float2 dv = yv;
                if (tau >= 2) {
                    float2 hv = hsm[0][tid];
                    dv.x -= hv.x; dv.y -= hv.y;
                }
                hsm[0][tid] = yv;
                const int gs = (tau + 2) % 3;   // t = tau-1
                G[gs].x += siggate(dv.x) * wt0;
                G[gs].y += siggate(dv.y) * wt0;
            }
            A1[s1] = make_float2(0.f, 0.f);
        }

        // conv2 completes y2(tau-2)
        if (tau <= T_ + 1) {
            const int s2 = (tau + 3) % 5;
            if (tau >= 2) {
                float2 yv = make_float2(A2[s2].x + bias1, A2[s2].y + bias1);
                float2 dv = yv;
                const int hs = 1 + (tau % 2);   // t = tau-2 -> t%2 == tau%2
                if (tau >= 4) {
                    float2 hv = hsm[hs][tid];
                    dv.x -= hv.x; dv.y -= hv.y;
                }
                hsm[hs][tid] = yv;
                const int gs = (tau + 1) % 3;   // t = tau-2
                G[gs].x += siggate(dv.x) * wt1;
                G[gs].y += siggate(dv.y) * wt1;
            }
            A2[s2] = make_float2(0.f, 0.f);
        }

        // conv3 completes y3(tau-3); gate for t=tau-3 done -> output
        {
            const int s3 = (tau + 4) % 7;
            if (tau >= 3) {
                float2 yv = make_float2(A3[s3].x + bias2, A3[s3].y + bias2);
                float2 dv = yv;
                const int hs = 3 + (tau % 3);   // t = tau-3 -> t%3 == tau%3
                if (tau >= 6) {
                    float2 hv = hsm[hs][tid];
                    dv.x -= hv.x; dv.y -= hv.y;
                }
                hsm[hs][tid] = yv;
                const int gs = tau % 3;         // t = tau-3
                float2 gt = G[gs];
                gt.x += siggate(dv.x) * wt2;
                gt.y += siggate(dv.y) * wt2;
                G[gs] = make_float2(0.f, 0.f);

                const int tout = tau - 3;
                const float* pc = &plane[(tau + 2) % SLOTS][0][0];  // plane tau-3
                float cx0 = pc[nb0 + RS + 1];
                float cx1 = pc[nb0 + RS + 2];
                float2 o = make_float2(cx0 * gt.x, cx1 * gt.y);
                *(float2*)(op + (size_t)tout * (H_ * W_) + obase) = o;
            }
            A3[s3] = make_float2(0.f, 0.f);
        }
    }
}

extern "C" void kernel_launch(void* const* d_in, const int* in_sizes, int n_in,
                              void* d_out, int out_size) {
    const float* x  = (const float*)d_in[0];
    const float* w1 = (const float*)d_in[1];
    const float* b1 = (const float*)d_in[2];
    const float* w2 = (const float*)d_in[3];
    const float* b2 = (const float*)d_in[4];
    const float* w3 = (const float*)d_in[5];
    const float* b3 = (const float*)d_in[6];
    const float* wg = (const float*)d_in[7];
    float* out = (float*)d_out;

    dim3 grid(B_ * C_ * NTILES);   // 4*64*7 = 1792 blocks
    dim3 block(NT);                // 224 threads
    tts_kernel<<<grid, block>>>(x, w1, b1, w2, b2, w3, b3, wg, out);
}